// round 9
// baseline (speedup 1.0000x reference)
#include <cuda_runtime.h>
#include <math.h>
#include <stdint.h>

// Q,K,V: [B=4, H=8, S=2048, Dh=64] fp32 ; src_batch_lens: [4] int32
// Flash attention, warp-tiled mma.sync m16n8k8 tf32, cp.async pipeline.
// K,V consumed as RAW fp32 bits (HMMA truncates to tf32); Q split 2-term rna.
// PV delayed one tile: QK(t) + PV(t-1) form one contiguous MMA stream and
// softmax(t)'s scalar chain hides under it. V triple-buffered for hazard-free
// 1-ahead prefetch; P warp-private single buffer (read-before-overwrite).

#define B_    4
#define H_    8
#define S_    2048
#define DH    64
#define BM    64     // q rows per CTA (16 per warp)
#define BN    64     // keys per smem tile
#define KSTR  68     // sK row stride (words): B-frag bank = 4g+j, distinct
#define VSTR  72     // sV row stride (words): B-frag bank = 8j+g, distinct
#define PSTR  68     // sP row stride (words)

#define KBUF  (BN * KSTR)
#define VBUF  (BN * VSTR)
#define SMEM_WORDS (2 * KBUF + 3 * VBUF + BM * PSTR)
#define SMEM_BYTES (SMEM_WORDS * 4)

__device__ __forceinline__ float ex2f(float x) {
    float r; asm("ex2.approx.f32 %0, %1;" : "=f"(r) : "f"(x)); return r;
}
__device__ __forceinline__ uint32_t f2tf(float x) {
    uint32_t r; asm("cvt.rna.tf32.f32 %0, %1;" : "=r"(r) : "f"(x)); return r;
}
__device__ __forceinline__ uint32_t s2u(const void* p) {
    uint32_t r;
    asm("{ .reg .u64 t; cvta.to.shared.u64 t, %1; cvt.u32.u64 %0, t; }"
        : "=r"(r) : "l"(p));
    return r;
}
__device__ __forceinline__ void cpa16(uint32_t dst, const void* src, int srcsz) {
    asm volatile("cp.async.cg.shared.global [%0], [%1], 16, %2;"
                 :: "r"(dst), "l"(src), "r"(srcsz));
}
#define CP_COMMIT() asm volatile("cp.async.commit_group;")
#define CP_WAIT0()  asm volatile("cp.async.wait_group 0;" ::: "memory")

__device__ __forceinline__ void mma_tf32(float d[4], const uint32_t a[4],
                                         const uint32_t b[2], const float c[4]) {
    asm("mma.sync.aligned.m16n8k8.row.col.f32.tf32.tf32.f32 "
        "{%0,%1,%2,%3},{%4,%5,%6,%7},{%8,%9},{%10,%11,%12,%13};"
        : "=f"(d[0]), "=f"(d[1]), "=f"(d[2]), "=f"(d[3])
        : "r"(a[0]), "r"(a[1]), "r"(a[2]), "r"(a[3]),
          "r"(b[0]), "r"(b[1]),
          "f"(c[0]), "f"(c[1]), "f"(c[2]), "f"(c[3]));
}

__global__ __launch_bounds__(128)
void sdpa_tf32_kernel(const float* __restrict__ Q,
                      const float* __restrict__ K,
                      const float* __restrict__ V,
                      const int*   __restrict__ lens,
                      float*       __restrict__ out)
{
    const float SCALE2 = 0.044194173824159216f * 1.4426950408889634f; // /sqrt(512)*log2e

    const int bh    = blockIdx.y;
    const int b     = bh >> 3;
    const int qtile = blockIdx.x;
    const int tid   = threadIdx.x;
    const int warp  = tid >> 5;
    const int lane  = tid & 31;
    const int g     = lane >> 2;
    const int j     = lane & 3;
    const int L     = lens[b];

    const size_t base = (size_t)bh * S_ * DH;
    const float* Qbh = Q + base;
    const float* Kbh = K + base;
    const float* Vbh = V + base;
    float*       Obh = out + base;

    extern __shared__ uint32_t smemraw[];
    uint32_t* sK0 = smemraw;
    uint32_t* sK1 = sK0 + KBUF;
    uint32_t* sVb[3];
    sVb[0] = sK1 + KBUF;
    sVb[1] = sVb[0] + VBUF;
    sVb[2] = sVb[1] + VBUF;
    uint32_t* sP  = sVb[2] + VBUF;       // Q stage, then per-warp P slices

    const uint32_t uK[2] = { s2u(sK0), s2u(sK1) };
    const uint32_t uV[3] = { s2u(sVb[0]), s2u(sVb[1]), s2u(sVb[2]) };

    const int ntiles = (L + BN - 1) / BN;

    const int crow = tid >> 4;       // base row, +8 per iteration
    const int cc4  = tid & 15;       // float4 column

    // ---- prologue: issue tile 0 ----
    #pragma unroll
    for (int i = 0; i < 8; i++) {
        int row = crow + i * 8;
        int ok  = row < L ? 16 : 0;
        int cr  = row < L ? row : 0;
        cpa16(uK[0] + (row * KSTR + cc4 * 4) * 4, Kbh + (size_t)cr * DH + cc4 * 4, ok);
        cpa16(uV[0] + (row * VSTR + cc4 * 4) * 4, Vbh + (size_t)cr * DH + cc4 * 4, ok);
    }
    CP_COMMIT();

    // ---- stage Q tile through sP, split into 2-term rna A-frags ----
    #pragma unroll
    for (int i = 0; i < 8; i++) {
        int row = crow + i * 8;
        float4 qv = ((const float4*)(Qbh + (size_t)(qtile * BM + row) * DH))[cc4];
        *(float4*)((float*)sP + row * PSTR + cc4 * 4) = qv;
    }
    __syncthreads();

    uint32_t qhi[8][4], qlo[8][4];
    {
        const float* qb = (const float*)sP + (warp * 16) * PSTR;
        #pragma unroll
        for (int ks = 0; ks < 8; ks++) {
            float v0 = qb[g       * PSTR + ks * 8 + j    ];
            float v1 = qb[(g + 8) * PSTR + ks * 8 + j    ];
            float v2 = qb[g       * PSTR + ks * 8 + j + 4];
            float v3 = qb[(g + 8) * PSTR + ks * 8 + j + 4];
            qhi[ks][0] = f2tf(v0); qlo[ks][0] = f2tf(v0 - __uint_as_float(qhi[ks][0]));
            qhi[ks][1] = f2tf(v1); qlo[ks][1] = f2tf(v1 - __uint_as_float(qhi[ks][1]));
            qhi[ks][2] = f2tf(v2); qlo[ks][2] = f2tf(v2 - __uint_as_float(qhi[ks][2]));
            qhi[ks][3] = f2tf(v3); qlo[ks][3] = f2tf(v3 - __uint_as_float(qhi[ks][3]));
        }
    }

    float O[8][4];
    #pragma unroll
    for (int dt = 0; dt < 8; dt++)
        #pragma unroll
        for (int e = 0; e < 4; e++) O[dt][e] = 0.f;
    float m0 = -INFINITY, m1 = -INFINITY;
    float l0 = 0.f, l1 = 0.f;

    uint32_t* pw = sP + (warp * 16) * PSTR;   // warp-private P slice
    const uint32_t* prevV = sVb[0];

    int vcur = 0;                     // t % 3
    for (int t = 0; t < ntiles; t++) {
        const int k0 = t * BN;
        const uint32_t* sK = (t & 1) ? sK1 : sK0;

        CP_WAIT0();          // tile t resident
        __syncthreads();     // visibility + all warps done with iter t-1 body

        // issue tile t+1 (K -> other K buf; V -> buf (t+1)%3, != (t-1)%3)
        if (t + 1 < ntiles) {
            const uint32_t uKn = uK[(t + 1) & 1];
            int vnext = vcur + 1; if (vnext == 3) vnext = 0;
            const uint32_t uVn = uV[vnext];
            const int kn = k0 + BN;
            #pragma unroll
            for (int i = 0; i < 8; i++) {
                int row = crow + i * 8;
                int gr  = kn + row;
                int ok  = gr < L ? 16 : 0;
                int cr  = gr < L ? gr : 0;
                cpa16(uKn + (row * KSTR + cc4 * 4) * 4, Kbh + (size_t)cr * DH + cc4 * 4, ok);
                cpa16(uVn + (row * VSTR + cc4 * 4) * 4, Vbh + (size_t)cr * DH + cc4 * 4, ok);
            }
        }
        CP_COMMIT();

        // ---- S = Q K^T : raw K bits as tf32 B-operands ----
        float Sacc[8][4];
        #pragma unroll
        for (int nt = 0; nt < 8; nt++)
            #pragma unroll
            for (int e = 0; e < 4; e++) Sacc[nt][e] = 0.f;

        #pragma unroll
        for (int ks = 0; ks < 8; ks++) {
            #pragma unroll
            for (int nt = 0; nt < 8; nt++) {
                const int r = (nt * 8 + g) * KSTR + ks * 8 + j;
                uint32_t bb[2] = { sK[r], sK[r + 4] };
                mma_tf32(Sacc[nt], qhi[ks], bb, Sacc[nt]);
                mma_tf32(Sacc[nt], qlo[ks], bb, Sacc[nt]);
            }
        }

        // ---- PV(t-1): independent of Sacc(t) -> keeps tensor pipe busy
        //      while the QK results and softmax chain resolve ----
        if (t > 0) {
            #pragma unroll
            for (int ks = 0; ks < 8; ks++) {
                const int pr = g * PSTR + ks * 8 + j;
                uint32_t a[4] = { pw[pr], pw[pr + 8 * PSTR],
                                  pw[pr + 4], pw[pr + 8 * PSTR + 4] };
                #pragma unroll
                for (int dt = 0; dt < 8; dt++) {
                    uint32_t bb[2] = { prevV[(ks * 8 + j    ) * VSTR + dt * 8 + g],
                                       prevV[(ks * 8 + j + 4) * VSTR + dt * 8 + g] };
                    mma_tf32(O[dt], a, bb, O[dt]);
                }
            }
        }

        // ---- scale + mask ----
        #pragma unroll
        for (int nt = 0; nt < 8; nt++)
            #pragma unroll
            for (int e = 0; e < 4; e++) Sacc[nt][e] *= SCALE2;

        if (k0 + BN > L) {
            #pragma unroll
            for (int nt = 0; nt < 8; nt++) {
                int col0 = k0 + nt * 8 + 2 * j;
                if (col0     >= L) { Sacc[nt][0] = -1e30f; Sacc[nt][2] = -1e30f; }
                if (col0 + 1 >= L) { Sacc[nt][1] = -1e30f; Sacc[nt][3] = -1e30f; }
            }
        }

        // ---- online softmax (O already contains tiles 0..t-1 at scale m(t-1)) ----
        float cm0 = Sacc[0][0], cm1 = Sacc[0][2];
        #pragma unroll
        for (int nt = 0; nt < 8; nt++) {
            cm0 = fmaxf(cm0, fmaxf(Sacc[nt][0], Sacc[nt][1]));
            cm1 = fmaxf(cm1, fmaxf(Sacc[nt][2], Sacc[nt][3]));
        }
        cm0 = fmaxf(cm0, __shfl_xor_sync(0xffffffffu, cm0, 1));
        cm0 = fmaxf(cm0, __shfl_xor_sync(0xffffffffu, cm0, 2));
        cm1 = fmaxf(cm1, __shfl_xor_sync(0xffffffffu, cm1, 1));
        cm1 = fmaxf(cm1, __shfl_xor_sync(0xffffffffu, cm1, 2));

        float mn0 = fmaxf(m0, cm0);
        float mn1 = fmaxf(m1, cm1);
        float sc0 = ex2f(m0 - mn0);   // first tile: ex2(-inf)=0
        float sc1 = ex2f(m1 - mn1);
        m0 = mn0; m1 = mn1;
        l0 *= sc0; l1 *= sc1;
        #pragma unroll
        for (int dt = 0; dt < 8; dt++) {
            O[dt][0] *= sc0; O[dt][1] *= sc0;
            O[dt][2] *= sc1; O[dt][3] *= sc1;
        }

        // ---- p = ex2(s-m), truncate to tf32 bits; l from TRUNCATED p.
        //      Overwrites P(t-1) AFTER PV(t-1) consumed it (same warp). ----
        #pragma unroll
        for (int nt = 0; nt < 8; nt++) {
            uint32_t t0 = __float_as_uint(ex2f(Sacc[nt][0] - m0)) & 0xFFFFE000u;
            uint32_t t1 = __float_as_uint(ex2f(Sacc[nt][1] - m0)) & 0xFFFFE000u;
            uint32_t t2 = __float_as_uint(ex2f(Sacc[nt][2] - m1)) & 0xFFFFE000u;
            uint32_t t3 = __float_as_uint(ex2f(Sacc[nt][3] - m1)) & 0xFFFFE000u;
            l0 += __uint_as_float(t0) + __uint_as_float(t1);
            l1 += __uint_as_float(t2) + __uint_as_float(t3);
            *(uint2*)(pw + g       * PSTR + nt * 8 + 2 * j) = make_uint2(t0, t1);
            *(uint2*)(pw + (g + 8) * PSTR + nt * 8 + 2 * j) = make_uint2(t2, t3);
        }
        __syncwarp();

        prevV = sVb[vcur];
        vcur = vcur + 1; if (vcur == 3) vcur = 0;
    }

    // ---- epilogue: final pending PV(ntiles-1) ----
    #pragma unroll
    for (int ks = 0; ks < 8; ks++) {
        const int pr = g * PSTR + ks * 8 + j;
        uint32_t a[4] = { pw[pr], pw[pr + 8 * PSTR],
                          pw[pr + 4], pw[pr + 8 * PSTR + 4] };
        #pragma unroll
        for (int dt = 0; dt < 8; dt++) {
            uint32_t bb[2] = { prevV[(ks * 8 + j    ) * VSTR + dt * 8 + g],
                               prevV[(ks * 8 + j + 4) * VSTR + dt * 8 + g] };
            mma_tf32(O[dt], a, bb, O[dt]);
        }
    }

    // ---- normalize (V-truncation mean bias corrected by 1+2^-11) ----
    l0 += __shfl_xor_sync(0xffffffffu, l0, 1);
    l0 += __shfl_xor_sync(0xffffffffu, l0, 2);
    l1 += __shfl_xor_sync(0xffffffffu, l1, 1);
    l1 += __shfl_xor_sync(0xffffffffu, l1, 2);
    const float BIAS = 1.00048828125f;
    float inv0 = BIAS / l0;
    float inv1 = BIAS / l1;

    const int qrow0 = qtile * BM + warp * 16;
    #pragma unroll
    for (int dt = 0; dt < 8; dt++) {
        int col = dt * 8 + 2 * j;
        float2 r0 = make_float2(O[dt][0] * inv0, O[dt][1] * inv0);
        float2 r1 = make_float2(O[dt][2] * inv1, O[dt][3] * inv1);
        *(float2*)(Obh + (size_t)(qrow0 + g    ) * DH + col) = r0;
        *(float2*)(Obh + (size_t)(qrow0 + g + 8) * DH + col) = r1;
    }
}

extern "C" void kernel_launch(void* const* d_in, const int* in_sizes, int n_in,
                              void* d_out, int out_size)
{
    const float* Q    = (const float*)d_in[0];
    const float* K    = (const float*)d_in[1];
    const float* V    = (const float*)d_in[2];
    const int*   lens = (const int*)  d_in[3];
    float*       out  = (float*)d_out;

    cudaFuncSetAttribute(sdpa_tf32_kernel,
                         cudaFuncAttributeMaxDynamicSharedMemorySize, SMEM_BYTES);

    dim3 grid(S_ / BM, B_ * H_);
    dim3 block(128);
    sdpa_tf32_kernel<<<grid, block, SMEM_BYTES>>>(Q, K, V, lens, out);
}